// round 15
// baseline (speedup 1.0000x reference)
#include <cuda_runtime.h>
#include <cuda_bf16.h>
#include <cstdint>
#include <cstring>
#include <math.h>

#define B_   8
#define M_   1024
#define H_   1024
#define NH_  16
#define HD_  64
#define HID_ 256

// ---------------- scratch (device globals; no allocations allowed) ----------
__device__ float g_v[B_*M_*H_];
__device__ float g_g[B_*M_*H_];
__device__ float g_hid[B_*M_*HID_];
__device__ float g_invsig[B_*M_];
__device__ float g_partial[B_*64*H_];
__device__ float g_colsum[B_*H_];
// preconverted operands (packed bf16 pairs as unsigned words)
__device__ unsigned g_xhi[B_*M_*H_/2];
__device__ unsigned g_xlo[B_*M_*H_/2];
__device__ unsigned g_wthi[(4*H_ + HID_) * (H_/2)];
__device__ unsigned g_wtlo[(4*H_ + HID_) * (H_/2)];
// q/k projections stored packed (d-pairs) for attention MMA
__device__ unsigned g_qhi[B_*M_*H_/2];
__device__ unsigned g_qlo[B_*M_*H_/2];
__device__ unsigned g_khi[B_*M_*H_/2];
__device__ unsigned g_klo[B_*M_*H_/2];

// ============================================================================
__device__ __forceinline__ void split2(float a, float b, unsigned& hi, unsigned& lo) {
    __nv_bfloat162 h = __floats2bfloat162_rn(a, b);
    float ra = a - __low2float(h);
    float rb = b - __high2float(h);
    __nv_bfloat162 l = __floats2bfloat162_rn(ra, rb);
    unsigned uh, ul;
    memcpy(&uh, &h, 4);
    memcpy(&ul, &l, 4);
    hi = uh; lo = ul;
}

__global__ __launch_bounds__(256) void conv_x_kernel(
    const float* __restrict__ x, unsigned* __restrict__ xhi, unsigned* __restrict__ xlo)
{
    size_t i = (size_t)blockIdx.x * 256 + threadIdx.x;
    float4 v = ((const float4*)x)[i];
    unsigned h0, l0, h1, l1;
    split2(v.x, v.y, h0, l0);
    split2(v.z, v.w, h1, l1);
    uint2 h; h.x = h0; h.y = h1;
    uint2 l; l.x = l0; l.y = l1;
    ((uint2*)xhi)[i] = h;
    ((uint2*)xlo)[i] = l;
}

__global__ __launch_bounds__(256) void conv_w_kernel(
    const float* __restrict__ W, int Nc,
    unsigned* __restrict__ wh, unsigned* __restrict__ wl)
{
    int idx = blockIdx.x * 256 + threadIdx.x;
    int n = idx >> 9, kp = idx & 511;
    float a = W[(size_t)(2 * kp) * Nc + n];
    float b = W[(size_t)(2 * kp + 1) * Nc + n];
    unsigned h, l;
    split2(a, b, h, l);
    wh[idx] = h;
    wl[idx] = l;
}

// ============================================================================
// Tensor-core GEMM (unchanged from R12)
// ============================================================================
#define PITCH_B32 20
#define PITCH_B16 40
#define TILE_B32  (128 * PITCH_B32)
#define GEMM_DYN  (8 * TILE_B32 * 4)

struct GArg  { const unsigned* wh; const unsigned* wl; const float* bias;
               float* out; unsigned* ohi; unsigned* olo; int packed; };
struct GArg4 { GArg g[4]; };

__device__ __forceinline__ void ldm_x4(unsigned* r, unsigned addr) {
    asm volatile("ldmatrix.sync.aligned.m8n8.x4.shared.b16 {%0,%1,%2,%3}, [%4];\n"
        : "=r"(r[0]), "=r"(r[1]), "=r"(r[2]), "=r"(r[3]) : "r"(addr));
}

__device__ __forceinline__ void mma16816(float* d, const unsigned* a,
                                         unsigned b0, unsigned b1) {
    asm volatile(
        "mma.sync.aligned.m16n8k16.row.col.f32.bf16.bf16.f32 "
        "{%0,%1,%2,%3}, {%4,%5,%6,%7}, {%8,%9}, {%0,%1,%2,%3};\n"
        : "+f"(d[0]), "+f"(d[1]), "+f"(d[2]), "+f"(d[3])
        : "r"(a[0]), "r"(a[1]), "r"(a[2]), "r"(a[3]), "r"(b0), "r"(b1));
}

__device__ __forceinline__ void stage_cp(
    int buf, int kc, int tid, unsigned sbase,
    const unsigned* baseAh, const unsigned* baseAl,
    const unsigned* baseBh, const unsigned* baseBl)
{
#pragma unroll
    for (int i = 0; i < 8; i++) {
        int id = i * 256 + tid;
        int tile = id >> 9;
        int rem = id & 511;
        int row = rem >> 2, c4 = rem & 3;
        const unsigned* bp = (tile == 0) ? baseAh
                           : (tile == 1) ? baseAl
                           : (tile == 2) ? baseBh : baseBl;
        const unsigned* src = bp + (size_t)row * 512 + kc * 16 + c4 * 4;
        unsigned dst = sbase +
            (unsigned)(((buf * 4 + tile) * TILE_B32 + row * PITCH_B32 + c4 * 4) * 4);
        asm volatile("cp.async.ca.shared.global [%0], [%1], 16;\n" :: "r"(dst), "l"(src));
    }
    asm volatile("cp.async.commit_group;\n");
}

__global__ __launch_bounds__(256, 2) void gemm_tc2(
    const unsigned* __restrict__ xhi, const unsigned* __restrict__ xlo,
    GArg4 args, int Nc)
{
    extern __shared__ unsigned smw[];
    const int tid = threadIdx.x;
    const int lane = tid & 31, warp = tid >> 5;
    const int wm = warp >> 2, wn = warp & 3;
    const int r0 = blockIdx.x * 128, n0 = blockIdx.y * 128;
    GArg ga = args.g[blockIdx.z];

    const unsigned sbase = (unsigned)__cvta_generic_to_shared(smw);
    const unsigned* baseAh = xhi + (size_t)r0 * 512;
    const unsigned* baseAl = xlo + (size_t)r0 * 512;
    const unsigned* baseBh = ga.wh + (size_t)n0 * 512;
    const unsigned* baseBl = ga.wl + (size_t)n0 * 512;

    const unsigned a_lane = (unsigned)((lane & 15) * PITCH_B16 + (lane >> 4) * 8);
    const unsigned b_lane = (unsigned)(((lane & 7) + ((lane >> 4) & 1) * 8) * PITCH_B16
                                       + ((lane >> 3) & 1) * 8);

    float acc[4][4][4];
#pragma unroll
    for (int i = 0; i < 4; i++)
#pragma unroll
        for (int j = 0; j < 4; j++)
#pragma unroll
            for (int c = 0; c < 4; c++) acc[i][j][c] = 0.f;

    stage_cp(0, 0, tid, sbase, baseAh, baseAl, baseBh, baseBl);

    for (int kc = 0; kc < 32; kc++) {
        const int cur = kc & 1;
        if (kc < 31) {
            stage_cp(cur ^ 1, kc + 1, tid, sbase, baseAh, baseAl, baseBh, baseBl);
            asm volatile("cp.async.wait_group 1;\n");
        } else {
            asm volatile("cp.async.wait_group 0;\n");
        }
        __syncthreads();

        const unsigned obAh = (unsigned)((cur * 4 + 0) * TILE_B32 * 4);
        const unsigned obAl = (unsigned)((cur * 4 + 1) * TILE_B32 * 4);
        const unsigned obBh = (unsigned)((cur * 4 + 2) * TILE_B32 * 4);
        const unsigned obBl = (unsigned)((cur * 4 + 3) * TILE_B32 * 4);

#pragma unroll
        for (int ks = 0; ks < 2; ks++) {
            unsigned af[4][4], bfr[2][4];
            const unsigned kso = (unsigned)(ks * 16);
#pragma unroll
            for (int mt = 0; mt < 4; mt++)
                ldm_x4(af[mt], sbase + obAh +
                       (a_lane + (unsigned)((wm * 64 + mt * 16) * PITCH_B16) + kso) * 2);
#pragma unroll
            for (int np = 0; np < 2; np++)
                ldm_x4(bfr[np], sbase + obBh +
                       (b_lane + (unsigned)((wn * 32 + np * 16) * PITCH_B16) + kso) * 2);
#pragma unroll
            for (int mt = 0; mt < 4; mt++)
#pragma unroll
                for (int nt = 0; nt < 4; nt++)
                    mma16816(acc[mt][nt], af[mt],
                             bfr[nt >> 1][(nt & 1) * 2], bfr[nt >> 1][(nt & 1) * 2 + 1]);
#pragma unroll
            for (int np = 0; np < 2; np++)
                ldm_x4(bfr[np], sbase + obBl +
                       (b_lane + (unsigned)((wn * 32 + np * 16) * PITCH_B16) + kso) * 2);
#pragma unroll
            for (int mt = 0; mt < 4; mt++)
#pragma unroll
                for (int nt = 0; nt < 4; nt++)
                    mma16816(acc[mt][nt], af[mt],
                             bfr[nt >> 1][(nt & 1) * 2], bfr[nt >> 1][(nt & 1) * 2 + 1]);
#pragma unroll
            for (int mt = 0; mt < 4; mt++)
                ldm_x4(af[mt], sbase + obAl +
                       (a_lane + (unsigned)((wm * 64 + mt * 16) * PITCH_B16) + kso) * 2);
#pragma unroll
            for (int np = 0; np < 2; np++)
                ldm_x4(bfr[np], sbase + obBh +
                       (b_lane + (unsigned)((wn * 32 + np * 16) * PITCH_B16) + kso) * 2);
#pragma unroll
            for (int mt = 0; mt < 4; mt++)
#pragma unroll
                for (int nt = 0; nt < 4; nt++)
                    mma16816(acc[mt][nt], af[mt],
                             bfr[nt >> 1][(nt & 1) * 2], bfr[nt >> 1][(nt & 1) * 2 + 1]);
        }
        __syncthreads();
    }

    const int gg = lane >> 2, tg = lane & 3;
#pragma unroll
    for (int mt = 0; mt < 4; mt++) {
#pragma unroll
        for (int nt = 0; nt < 4; nt++) {
            int row = r0 + wm * 64 + mt * 16 + gg;
            int col = n0 + wn * 32 + nt * 8 + tg * 2;
            float bx = ga.bias[col], by = ga.bias[col + 1];
            float v0x = acc[mt][nt][0] + bx, v0y = acc[mt][nt][1] + by;
            float v1x = acc[mt][nt][2] + bx, v1y = acc[mt][nt][3] + by;
            if (ga.packed) {
                unsigned h0, l0, h1, l1;
                split2(v0x, v0y, h0, l0);
                split2(v1x, v1y, h1, l1);
                size_t w0 = (size_t)row * (Nc >> 1) + (col >> 1);
                size_t w1 = (size_t)(row + 8) * (Nc >> 1) + (col >> 1);
                ga.ohi[w0] = h0; ga.olo[w0] = l0;
                ga.ohi[w1] = h1; ga.olo[w1] = l1;
            } else {
                float2 o0; o0.x = v0x; o0.y = v0y;
                float2 o1; o1.x = v1x; o1.y = v1y;
                *(float2*)(ga.out + (size_t)row * Nc + col) = o0;
                *(float2*)(ga.out + (size_t)(row + 8) * Nc + col) = o1;
            }
        }
    }
}

// ---------------- sigma ------------------------------------------------------
__global__ __launch_bounds__(256) void sigma_finish(
    const float* __restrict__ hid, const float* __restrict__ Wu2,
    const float* __restrict__ bu2, float* __restrict__ sig_out,
    float* __restrict__ invsig)
{
    const int row = blockIdx.x, t = threadIdx.x;
    __shared__ float red[256];
    float h = hid[(size_t)row * HID_ + t];
    red[t] = fmaxf(h, 0.f) * Wu2[t];
    __syncthreads();
    for (int s = 128; s > 0; s >>= 1) {
        if (t < s) red[t] += red[t + s];
        __syncthreads();
    }
    if (t == 0) {
        float tv = red[0] + bu2[0];
        float sp = (tv > 0.f) ? tv + log1pf(expf(-tv)) : log1pf(expf(tv));
        float sg = sp + 1e-6f;
        sig_out[row] = sg;
        invsig[row] = 1.f / sg;
    }
}

// ============================================================================
// Tensor-core fused attention, m-tile 16, 2 CTAs/SM
// ============================================================================
#define SP    1032
#define SS_W  (16*SP)                 // 16512 words fp32 score tile
#define QH_W  SS_W                    // [16][36]
#define QL_W  (QH_W + 16*36)
#define KB_W  (QL_W + 16*36)          // 17664
#define KHALF (128*36)                // 4608
// phase-3 reuse of K region:
#define VTH_W KB_W
#define VTL_W (VTH_W + 64*68)
#define CTX_W (VTL_W + 64*68)         // + 16*68
#define ATTN_DYN ((KB_W + 2*KHALF + 16*68) * 4)   // (17664+9216+1088)*4 = 111872 B

__device__ __forceinline__ void attn_stage_k16(
    const unsigned* __restrict__ khi, const unsigned* __restrict__ klo,
    int b, int h, int chunk, int tid, unsigned sbase)
{
#pragma unroll
    for (int it = 0; it < 8; it++) {
        int id = it * 256 + tid;
        int arr = id >> 10;
        int rem = id & 1023;
        int row = rem >> 3, gr = rem & 7;
        const unsigned* src = (arr ? klo : khi)
            + (size_t)(b * M_ + chunk * 128 + row) * 512 + h * 32 + gr * 4;
        unsigned dst = sbase +
            (unsigned)((KB_W + arr * KHALF + row * 36 + gr * 4) * 4);
        asm volatile("cp.async.ca.shared.global [%0], [%1], 16;\n" :: "r"(dst), "l"(src));
    }
    asm volatile("cp.async.commit_group;\n");
}

__global__ __launch_bounds__(256, 2) void attn_tc16(
    const unsigned* __restrict__ qhi, const unsigned* __restrict__ qlo,
    const unsigned* __restrict__ khi, const unsigned* __restrict__ klo,
    const float* __restrict__ vb, const float* __restrict__ gb,
    const float* __restrict__ invsig,
    float* __restrict__ attn_out, float* __restrict__ partial)
{
    extern __shared__ unsigned smw[];
    float* ssf = (float*)smw;
    __shared__ float isn[M_];

    const int mt = blockIdx.x, h = blockIdx.y, b = blockIdx.z;
    const int m0 = mt * 16;
    const int tid = threadIdx.x;
    const int lane = tid & 31, warp = tid >> 5;
    const unsigned sbase = (unsigned)__cvta_generic_to_shared(smw);

    for (int i = tid; i < M_; i += 256) isn[i] = invsig[b * M_ + i];
    const float ism0 = 0.125f * invsig[b * M_ + m0 + (lane >> 2)];
    const float ism1 = 0.125f * invsig[b * M_ + m0 + (lane >> 2) + 8];

    // ---- stage Q tile: 16 rows x 8 granules x {hi,lo} = 256 cp.async ----
    {
        int arr = tid >> 7, rem = tid & 127;
        int row = rem >> 3, gr = rem & 7;
        size_t gw = (size_t)(b * M_ + m0 + row) * 512 + h * 32 + gr * 4;
        const unsigned* src = (arr ? qlo : qhi) + gw;
        unsigned dst = sbase + (unsigned)(((arr ? QL_W : QH_W) + row * 36 + gr * 4) * 4);
        asm volatile("cp.async.ca.shared.global [%0], [%1], 16;\n" :: "r"(dst), "l"(src));
    }
    asm volatile("cp.async.commit_group;\n");

    const unsigned a_lane = (unsigned)((lane & 15) * 72 + (lane >> 4) * 8);
    const unsigned b_lane = (unsigned)(((lane & 7) + ((lane >> 4) & 1) * 8) * 72
                                       + ((lane >> 3) & 1) * 8);
    const unsigned qh_b = (unsigned)(QH_W * 4);
    const unsigned ql_b = (unsigned)(QL_W * 4);
    const unsigned kh_b = (unsigned)(KB_W * 4);
    const unsigned kl_b = kh_b + (unsigned)(KHALF * 4);

    // ---- phase 1: scores via MMA, 8 chunks of 128 n, single K buffer ----
    for (int c = 0; c < 8; c++) {
        attn_stage_k16(khi, klo, b, h, c, tid, sbase);
        asm volatile("cp.async.wait_group 0;\n");
        __syncthreads();

        float acc[2][4];
#pragma unroll
        for (int i = 0; i < 2; i++)
#pragma unroll
            for (int j = 0; j < 4; j++) acc[i][j] = 0.f;

#pragma unroll
        for (int ks = 0; ks < 4; ks++) {
            const unsigned kso = (unsigned)(ks * 16);
            unsigned ah[4], al[4], bh[4], bl[4];
            ldm_x4(ah, sbase + qh_b + (a_lane + kso) * 2);
            ldm_x4(al, sbase + ql_b + (a_lane + kso) * 2);
            unsigned ro = (unsigned)(warp * 16 * 72);
            ldm_x4(bh, sbase + kh_b + (b_lane + ro + kso) * 2);
            ldm_x4(bl, sbase + kl_b + (b_lane + ro + kso) * 2);
#pragma unroll
            for (int nt = 0; nt < 2; nt++) {
                unsigned h0 = bh[nt * 2], h1 = bh[nt * 2 + 1];
                unsigned l0 = bl[nt * 2], l1 = bl[nt * 2 + 1];
                mma16816(acc[nt], ah, h0, h1);
                mma16816(acc[nt], ah, l0, l1);
                mma16816(acc[nt], al, h0, h1);
            }
        }
        {
            int r = lane >> 2;
#pragma unroll
            for (int nt = 0; nt < 2; nt++) {
                int col = c * 128 + warp * 16 + nt * 8 + (lane & 3) * 2;
                float2 w0; w0.x = acc[nt][0] * ism0 * isn[col];
                w0.y = acc[nt][1] * ism0 * isn[col + 1];
                float2 w1; w1.x = acc[nt][2] * ism1 * isn[col];
                w1.y = acc[nt][3] * ism1 * isn[col + 1];
                *(float2*)&ssf[r * SP + col] = w0;
                *(float2*)&ssf[(r + 8) * SP + col] = w1;
            }
        }
        __syncthreads();
    }

    // ---- phase 2: softmax per row + attn gmem write ----
    for (int rr = 0; rr < 2; rr++) {
        int m = warp + 8 * rr;
        float* row = ssf + m * SP;
        float mx = -1e30f;
#pragma unroll
        for (int i = 0; i < 32; i++) mx = fmaxf(mx, row[lane + 32 * i]);
        for (int o = 16; o > 0; o >>= 1) mx = fmaxf(mx, __shfl_xor_sync(0xffffffffu, mx, o));
        float sum = 0.f;
#pragma unroll
        for (int i = 0; i < 32; i++) {
            float e = __expf(row[lane + 32 * i] - mx);
            row[lane + 32 * i] = e;
            sum += e;
        }
        for (int o = 16; o > 0; o >>= 1) sum += __shfl_xor_sync(0xffffffffu, sum, o);
        float inv = 1.f / sum;
        float* orow = attn_out + (((size_t)(b * NH_ + h)) * M_ + m0 + m) * M_;
#pragma unroll
        for (int cc = 0; cc < 8; cc++) {
            float4 v4 = *(float4*)(row + cc * 128 + lane * 4);
            v4.x *= inv; v4.y *= inv; v4.z *= inv; v4.w *= inv;
            *(float4*)(row + cc * 128 + lane * 4) = v4;
            *(float4*)(orow + cc * 128 + lane * 4) = v4;
        }
    }

    // ---- phase 3: ctx = attn @ V via MMA; each warp owns 8 d-columns ----
    float ctx[4];
#pragma unroll
    for (int j = 0; j < 4; j++) ctx[j] = 0.f;

    for (int c = 0; c < 8; c++) {
        __syncthreads();
#pragma unroll
        for (int u = 0; u < 4; u++) {
            int uu = u * 256 + tid;
            int np = uu & 63, dq = uu >> 6;
            int d = dq * 4;
            size_t gbase = (size_t)(b * M_ + c * 128 + 2 * np) * H_ + h * 64 + d;
            float4 v0 = *(const float4*)(vb + gbase);
            float4 v1 = *(const float4*)(vb + gbase + H_);
            unsigned hw, lw;
            split2(v0.x, v1.x, hw, lw);
            smw[VTH_W + (d + 0) * 68 + np] = hw; smw[VTL_W + (d + 0) * 68 + np] = lw;
            split2(v0.y, v1.y, hw, lw);
            smw[VTH_W + (d + 1) * 68 + np] = hw; smw[VTL_W + (d + 1) * 68 + np] = lw;
            split2(v0.z, v1.z, hw, lw);
            smw[VTH_W + (d + 2) * 68 + np] = hw; smw[VTL_W + (d + 2) * 68 + np] = lw;
            split2(v0.w, v1.w, hw, lw);
            smw[VTH_W + (d + 3) * 68 + np] = hw; smw[VTL_W + (d + 3) * 68 + np] = lw;
        }
        __syncthreads();

#pragma unroll
        for (int ks = 0; ks < 8; ks++) {
            int kn = c * 128 + ks * 16;
            int r = lane >> 2;
            int k0 = kn + (lane & 3) * 2;
            float2 f0 = *(float2*)&ssf[r * SP + k0];
            float2 f1 = *(float2*)&ssf[(r + 8) * SP + k0];
            float2 f2 = *(float2*)&ssf[r * SP + k0 + 8];
            float2 f3 = *(float2*)&ssf[(r + 8) * SP + k0 + 8];
            unsigned ah[4], al[4];
            split2(f0.x, f0.y, ah[0], al[0]);
            split2(f1.x, f1.y, ah[1], al[1]);
            split2(f2.x, f2.y, ah[2], al[2]);
            split2(f3.x, f3.y, ah[3], al[3]);
            int dr = warp * 8 + (lane >> 2);
            int wb = ks * 8 + (lane & 3);
            unsigned bh0 = smw[VTH_W + dr * 68 + wb];
            unsigned bh1 = smw[VTH_W + dr * 68 + wb + 4];
            unsigned bl0 = smw[VTL_W + dr * 68 + wb];
            unsigned bl1 = smw[VTL_W + dr * 68 + wb + 4];
            mma16816(ctx, ah, bh0, bh1);
            mma16816(ctx, ah, bl0, bl1);
            mma16816(ctx, al, bh0, bh1);
        }
    }

    // ---- ctx tile -> smem, gate-weighted column sums ----
    __syncthreads();
    {
        float* ctxt = (float*)(smw + CTX_W);
        int r = lane >> 2;
        int cb = warp * 8 + (lane & 3) * 2;
        float2 w;
        w.x = ctx[0]; w.y = ctx[1]; *(float2*)&ctxt[r * 68 + cb] = w;
        w.x = ctx[2]; w.y = ctx[3]; *(float2*)&ctxt[(r + 8) * 68 + cb] = w;
    }
    __syncthreads();
    if (tid < 64) {
        float* ctxt = (float*)(smw + CTX_W);
        float s = 0.f;
#pragma unroll
        for (int m = 0; m < 16; m++) {
            float cv = ctxt[m * 68 + tid];
            float gv = gb[(size_t)(b * M_ + m0 + m) * H_ + h * 64 + tid];
            s += cv / (1.f + __expf(-gv));
        }
        partial[((size_t)(b * 64 + mt)) * H_ + h * 64 + tid] = s;
    }
}

// ---------------- column-sum reduce (mean over m) ---------------------------
__global__ __launch_bounds__(256) void colsum_kernel(
    const float* __restrict__ partial, float* __restrict__ colsum)
{
    int b = blockIdx.y;
    int c = blockIdx.x * 256 + threadIdx.x;
    float s = 0.f;
#pragma unroll
    for (int t = 0; t < 64; t++) s += partial[((size_t)(b * 64 + t)) * H_ + c];
    colsum[b * H_ + c] = s * (1.f / 1024.f);
}

// ---------------- z = mean @ Wo + bo ----------------------------------------
__global__ __launch_bounds__(128) void zout_kernel(
    const float* __restrict__ colsum, const float* __restrict__ Wo,
    const float* __restrict__ bo, float* __restrict__ z)
{
    int b = blockIdx.y;
    int n = blockIdx.x * 128 + threadIdx.x;
    __shared__ float cs[H_];
    for (int i = threadIdx.x; i < H_; i += 128) cs[i] = colsum[b * H_ + i];
    __syncthreads();
    float acc = bo[n];
    for (int i = 0; i < H_; i++) acc = fmaf(cs[i], Wo[(size_t)i * H_ + n], acc);
    z[b * H_ + n] = acc;
}

// ---------------------------------------------------------------------------
extern "C" void kernel_launch(void* const* d_in, const int* in_sizes, int n_in,
                              void* d_out, int out_size)
{
    const float* x   = (const float*)d_in[0];
    const float* Wq  = (const float*)d_in[1];
    const float* bq  = (const float*)d_in[2];
    const float* Wk  = (const float*)d_in[3];
    const float* bk  = (const float*)d_in[4];
    const float* Wv  = (const float*)d_in[5];
    const float* bv  = (const float*)d_in[6];
    const float* Wg  = (const float*)d_in[7];
    const float* bg  = (const float*)d_in[8];
    const float* Wo  = (const float*)d_in[9];
    const float* bo  = (const float*)d_in[10];
    const float* Wu1 = (const float*)d_in[11];
    const float* bu1 = (const float*)d_in[12];
    const float* Wu2 = (const float*)d_in[13];
    const float* bu2 = (const float*)d_in[14];

    float* out      = (float*)d_out;
    float* z_out    = out;
    float* attn_out = out + B_ * H_;
    float* sig_out  = out + (size_t)out_size - B_ * M_;

    float *vp, *gp, *hp, *isp, *pp, *cp;
    unsigned *xhip, *xlop, *wthip, *wtlop, *qhip, *qlop, *khip, *klop;
    cudaGetSymbolAddress((void**)&vp, g_v);
    cudaGetSymbolAddress((void**)&gp, g_g);
    cudaGetSymbolAddress((void**)&hp, g_hid);
    cudaGetSymbolAddress((void**)&isp, g_invsig);
    cudaGetSymbolAddress((void**)&pp, g_partial);
    cudaGetSymbolAddress((void**)&cp, g_colsum);
    cudaGetSymbolAddress((void**)&xhip, g_xhi);
    cudaGetSymbolAddress((void**)&xlop, g_xlo);
    cudaGetSymbolAddress((void**)&wthip, g_wthi);
    cudaGetSymbolAddress((void**)&wtlop, g_wtlo);
    cudaGetSymbolAddress((void**)&qhip, g_qhi);
    cudaGetSymbolAddress((void**)&qlop, g_qlo);
    cudaGetSymbolAddress((void**)&khip, g_khi);
    cudaGetSymbolAddress((void**)&klop, g_klo);

    cudaFuncSetAttribute(attn_tc16, cudaFuncAttributeMaxDynamicSharedMemorySize, ATTN_DYN);
    cudaFuncSetAttribute(gemm_tc2, cudaFuncAttributeMaxDynamicSharedMemorySize, GEMM_DYN);

    const size_t WROW = H_ / 2;
    conv_x_kernel<<<B_*M_*H_/4/256, 256>>>(x, xhip, xlop);
    conv_w_kernel<<<2*H_, 256>>>(Wq,  H_,   wthip + 0*H_*WROW, wtlop + 0*H_*WROW);
    conv_w_kernel<<<2*H_, 256>>>(Wk,  H_,   wthip + 1*H_*WROW, wtlop + 1*H_*WROW);
    conv_w_kernel<<<2*H_, 256>>>(Wv,  H_,   wthip + 2*H_*WROW, wtlop + 2*H_*WROW);
    conv_w_kernel<<<2*H_, 256>>>(Wg,  H_,   wthip + 3*H_*WROW, wtlop + 3*H_*WROW);
    conv_w_kernel<<<2*HID_, 256>>>(Wu1, HID_, wthip + 4*H_*WROW, wtlop + 4*H_*WROW);

    GArg4 a4;
    a4.g[0].wh = wthip + 0*H_*WROW; a4.g[0].wl = wtlop + 0*H_*WROW; a4.g[0].bias = bq;
    a4.g[0].out = nullptr; a4.g[0].ohi = qhip; a4.g[0].olo = qlop; a4.g[0].packed = 1;
    a4.g[1].wh = wthip + 1*H_*WROW; a4.g[1].wl = wtlop + 1*H_*WROW; a4.g[1].bias = bk;
    a4.g[1].out = nullptr; a4.g[1].ohi = khip; a4.g[1].olo = klop; a4.g[1].packed = 1;
    a4.g[2].wh = wthip + 2*H_*WROW; a4.g[2].wl = wtlop + 2*H_*WROW; a4.g[2].bias = bv;
    a4.g[2].out = vp; a4.g[2].ohi = nullptr; a4.g[2].olo = nullptr; a4.g[2].packed = 0;
    a4.g[3].wh = wthip + 3*H_*WROW; a4.g[3].wl = wtlop + 3*H_*WROW; a4.g[3].bias = bg;
    a4.g[3].out = gp; a4.g[3].ohi = nullptr; a4.g[3].olo = nullptr; a4.g[3].packed = 0;
    gemm_tc2<<<dim3(64, 8, 4), 256, GEMM_DYN>>>(xhip, xlop, a4, H_);

    GArg4 au;
    au.g[0].wh = wthip + 4*H_*WROW; au.g[0].wl = wtlop + 4*H_*WROW; au.g[0].bias = bu1;
    au.g[0].out = hp; au.g[0].ohi = nullptr; au.g[0].olo = nullptr; au.g[0].packed = 0;
    au.g[1] = au.g[0]; au.g[2] = au.g[0]; au.g[3] = au.g[0];
    gemm_tc2<<<dim3(64, 2, 1), 256, GEMM_DYN>>>(xhip, xlop, au, HID_);

    sigma_finish<<<B_ * M_, 256>>>(hp, Wu2, bu2, sig_out, isp);

    attn_tc16<<<dim3(64, 16, 8), 256, ATTN_DYN>>>(qhip, qlop, khip, klop,
                                                  vp, gp, isp, attn_out, pp);

    colsum_kernel<<<dim3(4, 8), 256>>>(pp, cp);
    zout_kernel<<<dim3(8, 8), 128>>>(cp, Wo, bo, z_out);
}